// round 5
// baseline (speedup 1.0000x reference)
#include <cuda_runtime.h>
#include <math.h>

// ---------------- Problem constants ----------------
#define BATCH 32
#define CIN   64
#define HIN   64
#define WIN   64
#define KOUT  128
#define OHH   62
#define OWW   62
#define LOC   3844            // OHH*OWW
#define BL    123008          // BATCH*LOC
#define RDIM  576             // CIN*3*3
#define HW    4096            // HIN*WIN
#define Y_ELEMS 15745024      // BATCH*KOUT*LOC

typedef unsigned long long u64;

// ---------------- Scratch (no allocations allowed) ----------------
__device__ float g_wT[RDIM * KOUT];   // normalized weight, layout [r][k]
__device__ float g_winv[KOUT];
__device__ int   g_winner[BL];
__device__ int   g_counts[KOUT];
__device__ int   g_offsets[KOUT + 1];
__device__ int   g_cursor[KOUT];
__device__ int   g_list[BL];

// f32x2 helpers (sm_100a packed fp32)
__device__ __forceinline__ u64 pack_dup(float x) {
    u64 r;
    asm("mov.b64 %0, {%1, %2};" : "=l"(r) : "f"(x), "f"(x));
    return r;
}
__device__ __forceinline__ void fma2(u64& d, u64 a, u64 b) {
    asm("fma.rn.f32x2 %0, %1, %2, %0;" : "+l"(d) : "l"(a), "l"(b));
}
__device__ __forceinline__ float2 unpack2(u64 v) {
    float2 r;
    asm("mov.b64 {%0, %1}, %2;" : "=f"(r.x), "=f"(r.y) : "l"(v));
    return r;
}

// ---------------- 1a) per-k inverse weight norm ----------------
__global__ void norm_kernel(const float* __restrict__ w) {
    int k = blockIdx.x;
    int tid = threadIdx.x;
    __shared__ float red[256];
    float s = 0.f;
    for (int t = tid; t < RDIM; t += 256) { float v = w[k * RDIM + t]; s += v * v; }
    red[tid] = s;
    __syncthreads();
    for (int off = 128; off > 0; off >>= 1) {
        if (tid < off) red[tid] += red[tid + off];
        __syncthreads();
    }
    if (tid == 0) {
        float n = sqrtf(red[0]);
        g_winv[k] = (n == 0.f) ? 1.f : (1.f / n);
    }
}

// ---------------- 1b) transpose normalized weights, zero wu ----------------
__global__ void wtrans_kernel(const float* __restrict__ w, float* __restrict__ wu) {
    int k = blockIdx.x;
    int tid = threadIdx.x;
    float iv = g_winv[k];
    for (int t = tid; t < RDIM; t += 256) {
        g_wT[t * KOUT + k] = w[k * RDIM + t] * iv;
        wu[k * RDIM + t] = 0.f;
    }
}

// ---------------- 1c) zero winner counters ----------------
__global__ void zcnt_kernel() { g_counts[threadIdx.x] = 0; }

// ---------------- 2) conv + fused argmax/count (f32x2, dup-x in smem) ----------------
// CTA: all 128 k x (4 rows x 32 cols). Thread: k = 2*tx + 32*q + r, 8 cols.
// Channel chunks of 4 to fit dup-x + weights in static smem.
#define TOH 4
#define TOW 32
#define CCH 4                             // channels per chunk
#define NCHUNK (CIN / CCH)                // 16

__global__ __launch_bounds__(256, 2)
void conv_kernel(const float* __restrict__ x, const float* __restrict__ bias,
                 float* __restrict__ y) {
    __shared__ __align__(16) u64 sXd[CCH][6][36];   // dup pairs: 6.9KB
    __shared__ float sW[CCH * 9][KOUT];             // 18.4KB
    __shared__ int scount[KOUT];

    int tid = threadIdx.x;
    int tx = tid & 15;               // k-lane
    int ty = tid >> 4;               // loc-group
    int b   = blockIdx.z;
    int oh0 = blockIdx.y * TOH;
    int ow0 = blockIdx.x * TOW;
    int kb   = tx * 2;               // pair base; groups at kb + 32*q
    int lrow = ty >> 2;              // 0..3
    int c0   = (ty & 3) * 8;         // 0,8,16,24

    if (tid < KOUT) scount[tid] = 0;

    u64 acc[4][8];                   // [q][u] = (k=kb+32q, k=kb+32q+1)
#pragma unroll
    for (int q = 0; q < 4; q++) {
        u64 bv = *(const u64*)(bias + kb + 32 * q);   // 8B-aligned (kb even)
#pragma unroll
        for (int u = 0; u < 8; u++) acc[q][u] = bv;
    }

    const float* xb = x + (size_t)b * (CIN * HW);

    for (int cb = 0; cb < NCHUNK; cb++) {     // 16 chunks of 4 channels
        __syncthreads();
        // stage x tile as dup pairs: 4ch x 6rows x 34cols -> 240 slots
        for (int slot = tid; slot < CCH * 6 * 10; slot += 256) {
            int row = slot / 10, sub = slot % 10;
            int c = row / 6, rr = row % 6;
            int h = oh0 + rr;
            if (sub < 8) {
                int col = sub * 4;
                float4 v = make_float4(0.f, 0.f, 0.f, 0.f);
                if (h < HIN) v = *(const float4*)(xb + (cb * CCH + c) * HW + h * WIN + ow0 + col);
                ulonglong2 p0, p1;
                p0.x = pack_dup(v.x); p0.y = pack_dup(v.y);
                p1.x = pack_dup(v.z); p1.y = pack_dup(v.w);
                *(ulonglong2*)&sXd[c][rr][col]     = p0;   // 16B aligned (col even)
                *(ulonglong2*)&sXd[c][rr][col + 2] = p1;
            } else {
                int col = 32 + (sub - 8);
                int wcol = ow0 + col;
                float v = 0.f;
                if (h < HIN && wcol < WIN) v = xb[(cb * CCH + c) * HW + h * WIN + wcol];
                sXd[c][rr][col] = pack_dup(v);
            }
        }
        // stage weights: contiguous 36x128 slab of g_wT
        {
            const float4* src = (const float4*)(g_wT + cb * (CCH * 9) * KOUT);
            float4* dst = (float4*)(&sW[0][0]);
            for (int idx = tid; idx < CCH * 9 * (KOUT / 4); idx += 256) dst[idx] = src[idx];
        }
        __syncthreads();

        for (int cc = 0; cc < CCH; cc++) {    // rolled: keeps body inside L0 I$
#pragma unroll
            for (int i = 0; i < 3; i++) {
                u64 xd[10];
#pragma unroll
                for (int m = 0; m < 10; m += 2) {        // 5x LDS.128
                    ulonglong2 t2 = *(const ulonglong2*)&sXd[cc][lrow + i][c0 + m];
                    xd[m] = t2.x; xd[m + 1] = t2.y;
                }
#pragma unroll
                for (int j = 0; j < 3; j++) {
                    const float* wrow = &sW[cc * 9 + i * 3 + j][0];
                    u64 w2[4];
#pragma unroll
                    for (int q = 0; q < 4; q++)
                        w2[q] = *(const u64*)(wrow + kb + 32 * q);  // contiguous 128B across lanes
#pragma unroll
                    for (int q = 0; q < 4; q++)
#pragma unroll
                        for (int u = 0; u < 8; u++)
                            fma2(acc[q][u], w2[q], xd[j + u]);
                }
            }
        }
    }

    int oh = oh0 + lrow;
    bool rowok = (oh < OHH);

    // fused argmax per location
#pragma unroll
    for (int u = 0; u < 8; u++) {
        int ow = ow0 + c0 + u;
        float2 v0 = unpack2(acc[0][u]);
        float best = v0.x; int bk = kb;
        if (v0.y > best) { best = v0.y; bk = kb + 1; }
#pragma unroll
        for (int q = 1; q < 4; q++) {
            float2 v = unpack2(acc[q][u]);
            int kq = kb + 32 * q;
            if (v.x > best) { best = v.x; bk = kq; }
            if (v.y > best) { best = v.y; bk = kq + 1; }
        }
#pragma unroll
        for (int o = 1; o < 16; o <<= 1) {    // butterfly over 16 k-lanes, first-max tiebreak
            float v2 = __shfl_xor_sync(0xffffffffu, best, o);
            int   k2 = __shfl_xor_sync(0xffffffffu, bk,   o);
            if (v2 > best || (v2 == best && k2 < bk)) { best = v2; bk = k2; }
        }
        if (rowok && ow < OWW && tx == 0) {
            g_winner[b * LOC + oh * OWW + ow] = bk;
            atomicAdd(&scount[bk], 1);
        }
    }

    // y stores
    if (rowok) {
#pragma unroll
        for (int q = 0; q < 4; q++) {
            int k = kb + 32 * q;
            float* yp0 = y + ((size_t)(b * KOUT + k)) * LOC + oh * OWW + ow0 + c0;
            float* yp1 = yp0 + LOC;
#pragma unroll
            for (int u = 0; u < 8; u++) {
                if (ow0 + c0 + u < OWW) {
                    float2 v = unpack2(acc[q][u]);
                    yp0[u] = v.x;
                    yp1[u] = v.y;
                }
            }
        }
    }

    __syncthreads();
    if (tid < KOUT && scount[tid]) atomicAdd(&g_counts[tid], scount[tid]);
}

// ---------------- 3) exclusive scan of counts (parallel, 128 threads) ----------------
__global__ void scan_kernel() {
    int t = threadIdx.x;               // 128
    int lane = t & 31, w = t >> 5;
    int v = g_counts[t];
    int inc = v;
#pragma unroll
    for (int o = 1; o < 32; o <<= 1) {
        int n = __shfl_up_sync(0xffffffffu, inc, o);
        if (lane >= o) inc += n;
    }
    __shared__ int wsum[4];
    if (lane == 31) wsum[w] = inc;
    __syncthreads();
    int add = 0;
#pragma unroll
    for (int i = 0; i < 4; i++) if (i < w) add += wsum[i];
    int excl = inc - v + add;
    g_offsets[t] = excl;
    g_cursor[t] = excl;
    if (t == 127) g_offsets[KOUT] = excl + v;
}

// ---------------- 4) scatter locations into per-k lists (warp-aggregated) ----------------
__global__ void scatter_kernel() {
    int gloc = blockIdx.x * 128 + threadIdx.x;
    int k = g_winner[gloc];
    unsigned m = __match_any_sync(0xffffffffu, k);
    int lane = threadIdx.x & 31;
    int leader = __ffs(m) - 1;
    int prefix = __popc(m & ((1u << lane) - 1u));
    int base = 0;
    if (lane == leader) base = atomicAdd(&g_cursor[k], __popc(m));
    base = __shfl_sync(0xffffffffu, base, leader);
    g_list[base + prefix] = gloc;
}

// ---------------- 5) Hebbian gather: wu[k,r] = scale * sum_{loc in list_k} patch[r] ----------------
#define NSPLIT 8
__global__ __launch_bounds__(192)
void hebb_kernel(const float* __restrict__ x, float* __restrict__ wu) {
    int k = blockIdx.y;
    int start = g_offsets[k], end = g_offsets[k + 1];
    int len = end - start;
    int s0 = start + (int)((long long)len * blockIdx.x / NSPLIT);
    int s1 = start + (int)((long long)len * (blockIdx.x + 1) / NSPLIT);
    int t = threadIdx.x;

    int off[3];
    float a[3] = {0.f, 0.f, 0.f};
#pragma unroll
    for (int q = 0; q < 3; q++) {
        int r = t + q * 192;
        int c = r / 9, rem = r % 9;
        off[q] = c * HW + (rem / 3) * WIN + (rem % 3);
    }

    if (s0 < s1) {
        int nextg = g_list[s0];                     // prefetch list head
        for (int p = s0; p < s1; p++) {
            int gloc = nextg;
            if (p + 1 < s1) nextg = g_list[p + 1];  // hide broadcast LDG behind body
            int b = gloc / LOC;
            int il = gloc - b * LOC;
            int oh = il / OWW;
            int ow = il - oh * OWW;
            const float* px = x + (size_t)b * (CIN * HW) + oh * WIN + ow;
            a[0] += px[off[0]];
            a[1] += px[off[1]];
            a[2] += px[off[2]];
        }
    }

    const float scale = 1.0f / 123008.0f;      // 1/(B*L + 1e-8) == 1/123008 in fp32
#pragma unroll
    for (int q = 0; q < 3; q++)
        atomicAdd(&wu[k * RDIM + t + q * 192], a[q] * scale);
}

// ---------------- launch ----------------
// Order matters: ncu capture lands on the 4th launch -> conv gets profiled.
extern "C" void kernel_launch(void* const* d_in, const int* in_sizes, int n_in,
                              void* d_out, int out_size) {
    const float* x    = (const float*)d_in[0];   // [32,64,64,64]
    const float* w    = (const float*)d_in[1];   // [128,64,3,3]
    const float* bias = (const float*)d_in[2];   // [128]
    float* y  = (float*)d_out;                   // [32,128,62,62]
    float* wu = y + (size_t)Y_ELEMS;             // [128,64,3,3]

    norm_kernel<<<KOUT, 256>>>(w);               // 1
    wtrans_kernel<<<KOUT, 256>>>(w, wu);         // 2
    zcnt_kernel<<<1, KOUT>>>();                  // 3
    conv_kernel<<<dim3(2, 16, BATCH), 256>>>(x, bias, y);  // 4  <- profiled slot
    scan_kernel<<<1, 128>>>();                   // 5
    scatter_kernel<<<BL / 128, 128>>>();         // 6
    hebb_kernel<<<dim3(NSPLIT, KOUT), 192>>>(x, wu);       // 7
}

// round 9
// speedup vs baseline: 1.1985x; 1.1985x over previous
#include <cuda_runtime.h>
#include <cuda_bf16.h>
#include <math.h>

// ---------------- Problem constants ----------------
#define BATCH 32
#define CIN   64
#define HIN   64
#define WIN   64
#define KOUT  128
#define OHH   62
#define OWW   62
#define LOC   3844            // OHH*OWW
#define BL    123008          // BATCH*LOC
#define RDIM  576             // CIN*3*3
#define HW    4096            // HIN*WIN
#define Y_ELEMS 15745024      // BATCH*KOUT*LOC

typedef unsigned long long u64;
typedef unsigned int u32;

// ---------------- Precomputed operands (module globals) ----------------
// X splits: [s][b][h][w(66, zero-pad 64/65)][c] bf16, c contiguous (k-major for B)
#define XSPLIT (32 * 64 * 66 * 64)              // halves per split
__device__ __align__(16) unsigned short g_xs[2 * XSPLIT];   // ~34.6MB
// W splits: [tap][s][n][c] bf16, c contiguous (k-major for A)
__device__ __align__(16) unsigned short g_ws[9 * 2 * KOUT * CIN];
__device__ float g_wT[RDIM * KOUT];   // normalized fp32 weights, [r][k] (refine path)

__device__ float g_winv[KOUT];
__device__ int   g_winner[BL];
__device__ int   g_counts[KOUT];
__device__ int   g_offsets[KOUT + 1];
__device__ int   g_cursor[KOUT];
__device__ int   g_list[BL];
__device__ int   g_nrefine;
__device__ int   g_refine[BL];

#define RTHRESH 0.005f        // near-tie gap threshold (~100x max y abs error)

// ---------------- PTX helpers (all sm_80-level; compile for plain sm_100) ----------------
__device__ __forceinline__ u32 smem_u32(const void* p) {
    u32 a;
    asm("{ .reg .u64 t; cvta.to.shared.u64 t, %1; cvt.u32.u64 %0, t; }" : "=r"(a) : "l"(p));
    return a;
}
__device__ __forceinline__ void cpa16(u32 dst, const void* src) {
    asm volatile("cp.async.cg.shared.global [%0], [%1], 16;" :: "r"(dst), "l"(src));
}
#define CP_COMMIT() asm volatile("cp.async.commit_group;" ::: "memory")
#define CP_WAIT0()  asm volatile("cp.async.wait_group 0;" ::: "memory")

__device__ __forceinline__ void ldmx4(u32* r, u32 addr) {
    asm volatile("ldmatrix.sync.aligned.m8n8.x4.shared.b16 {%0,%1,%2,%3}, [%4];"
                 : "=r"(r[0]), "=r"(r[1]), "=r"(r[2]), "=r"(r[3]) : "r"(addr));
}
__device__ __forceinline__ void ldmx2(u32* r, u32 addr) {
    asm volatile("ldmatrix.sync.aligned.m8n8.x2.shared.b16 {%0,%1}, [%2];"
                 : "=r"(r[0]), "=r"(r[1]) : "r"(addr));
}
// D(16x8,f32) += A(16x16,bf16 row) * B(16x8,bf16 col)
__device__ __forceinline__ void mma16816(float* d, const u32* a, const u32* b) {
    asm volatile("mma.sync.aligned.m16n8k16.row.col.f32.bf16.bf16.f32 "
                 "{%0,%1,%2,%3}, {%4,%5,%6,%7}, {%8,%9}, {%0,%1,%2,%3};"
                 : "+f"(d[0]), "+f"(d[1]), "+f"(d[2]), "+f"(d[3])
                 : "r"(a[0]), "r"(a[1]), "r"(a[2]), "r"(a[3]), "r"(b[0]), "r"(b[1]));
}

// ---------------- 1) weight inverse norms + zero counters ----------------
__global__ void norm_kernel(const float* __restrict__ w) {
    int k = blockIdx.x;
    int tid = threadIdx.x;
    __shared__ float red[256];
    float s = 0.f;
    for (int t = tid; t < RDIM; t += 256) { float v = w[k * RDIM + t]; s += v * v; }
    red[tid] = s;
    __syncthreads();
    for (int off = 128; off > 0; off >>= 1) {
        if (tid < off) red[tid] += red[tid + off];
        __syncthreads();
    }
    if (tid == 0) {
        float n = sqrtf(red[0]);
        g_winv[k] = (n == 0.f) ? 1.f : (1.f / n);
    }
    if (blockIdx.x == 0 && tid < KOUT) g_counts[tid] = 0;
    if (blockIdx.x == 0 && tid == 0) g_nrefine = 0;
}

// ---------------- 2) build split weight operands + fp32 wT + zero wu ----------------
__global__ void wbuild_kernel(const float* __restrict__ w, float* __restrict__ wu) {
    int bx = blockIdx.x, tid = threadIdx.x;
    if (bx < 18) {
        int tap = bx >> 1, s = bx & 1;
        int i = tap / 3, j = tap % 3;
        for (int e = tid; e < KOUT * CIN; e += 256) {
            int n = e >> 6, c = e & 63;
            float wn = w[((n * 64 + c) * 3 + i) * 3 + j] * g_winv[n];
            __nv_bfloat16 hb = __float2bfloat16(wn);
            __nv_bfloat16 out = (s == 0) ? hb : __float2bfloat16(wn - __bfloat162float(hb));
            g_ws[((tap * 2 + s) * KOUT + n) * CIN + c] = __bfloat16_as_ushort(out);
            if (s == 0) g_wT[(c * 9 + tap) * KOUT + n] = wn;   // [r][k] for refine
        }
    } else {
        for (int idx = (bx - 18) * 256 + tid; idx < KOUT * RDIM; idx += 32 * 256)
            wu[idx] = 0.f;
    }
}

// ---------------- 3) build transposed/split X operand ----------------
__global__ void xbuild_kernel(const float* __restrict__ x) {
    __shared__ float plane[64 * 65];
    int bh = blockIdx.x;                    // b*64 + h
    int b = bh >> 6, h = bh & 63;
    int tid = threadIdx.x;
    for (int idx = tid; idx < 4096; idx += 256) {
        int c = idx >> 6, ww = idx & 63;
        plane[c * 65 + ww] = x[((size_t)(b * 64 + c) * 64 + h) * 64 + ww];
    }
    __syncthreads();
    size_t rowbase = (size_t)bh * 66 * 64;
    for (int idx = tid; idx < 66 * 64; idx += 256) {
        int ww = idx >> 6, c = idx & 63;
        float v = (ww < 64) ? plane[c * 65 + ww] : 0.f;
        __nv_bfloat16 hb = __float2bfloat16(v);
        __nv_bfloat16 lb = __float2bfloat16(v - __bfloat162float(hb));
        g_xs[rowbase + (size_t)ww * 64 + c]          = __bfloat16_as_ushort(hb);
        g_xs[XSPLIT + rowbase + (size_t)ww * 64 + c] = __bfloat16_as_ushort(lb);
    }
}

// ---------------- 4) HMMA conv: 9 taps x 3 split products ----------------
// CTA (ohp, b): M=128 k x N=128 locs (2 oh x 64 ww), K=64/tap.
// 8 warps = 4m x 2n; warp tile m32 x n64.
#define SX_ROWS 264                 // 4 h-rows x 66 w
#define ROWH 72                     // smem row = 144B (conflict-free ldmatrix)
#define SW_BYTE_OFF (2 * SX_ROWS * ROWH * 2)        // 76032
#define SMEM_BYTES (SW_BYTE_OFF + 2 * 2 * KOUT * ROWH * 2)  // 149760

__global__ __launch_bounds__(256, 1)
void conv_mma_kernel(const float* __restrict__ bias, float* __restrict__ y) {
    extern __shared__ __align__(16) unsigned short sm[];
    u32 smb = smem_u32(sm);
    int tid = threadIdx.x;
    int warp = tid >> 5, lane = tid & 31;
    int wm = warp >> 1, wn = warp & 1;
    int m0 = wm * 32;
    int ohp = blockIdx.x, b = blockIdx.y;
    int oh0 = ohp * 2;
    int lane16 = lane & 15;

    // ---- stage X (both splits) + W tap0 into buf0 ----
    {
        size_t xg = ((size_t)(b * 64 + oh0) * 66) * 128;   // bytes into a split
        const char* x0 = (const char*)g_xs + xg;
        const char* x1 = (const char*)g_xs + (size_t)XSPLIT * 2 + xg;
        for (int i = tid; i < SX_ROWS * 8; i += 256) {      // 2112 chunks per split
            u32 d0 = smb + (i >> 3) * 144 + (i & 7) * 16;
            cpa16(d0, x0 + (size_t)i * 16);
            cpa16(d0 + SX_ROWS * 144, x1 + (size_t)i * 16);
        }
        const char* wsrc = (const char*)g_ws;               // tap 0
        for (int i = tid; i < 2048; i += 256) {
            cpa16(smb + SW_BYTE_OFF + (i >> 3) * 144 + (i & 7) * 16, wsrc + i * 16);
        }
        CP_COMMIT();
        CP_WAIT0();
        __syncthreads();
    }

    float acc[2][8][4];
#pragma unroll
    for (int mi = 0; mi < 2; mi++)
#pragma unroll
        for (int f = 0; f < 8; f++)
#pragma unroll
            for (int e = 0; e < 4; e++) acc[mi][f][e] = 0.f;

    for (int t = 0; t < 9; t++) {
        int buf = t & 1;
        if (t < 8) {                                        // prefetch next tap
            const char* wsrc = (const char*)g_ws + (size_t)(t + 1) * 32768;
            u32 dbase = smb + SW_BYTE_OFF + (buf ^ 1) * (256 * 144);
            for (int i = tid; i < 2048; i += 256)
                cpa16(dbase + (i >> 3) * 144 + (i & 7) * 16, wsrc + i * 16);
            CP_COMMIT();
        }

        int i_t = t / 3, j_t = t % 3;
        // A: row-major W[n][c], row = m0 + 16*mi + lane%16, col16 = lane/16
        u32 ab = smb + SW_BYTE_OFF + (buf * 256) * 144 + (m0 + (lane & 15)) * 144 + (lane >> 4) * 16;
        // B: rows = (wn+i)*66 + (8f + lane16%8 + j), col16 = lane16/8
        u32 bb = smb + ((wn + i_t) * 66 + j_t + (lane16 & 7)) * 144 + (lane16 >> 3) * 16;

#pragma unroll
        for (int k16 = 0; k16 < 4; k16++) {
            u32 col = k16 * 32;
            u32 ah[2][4], al[2][4];
            ldmx4(ah[0], ab + col);                       // s=0 (hi), mi=0
            ldmx4(ah[1], ab + 16 * 144 + col);            // s=0, mi=1
            ldmx4(al[0], ab + 128 * 144 + col);           // s=1 (lo), mi=0
            ldmx4(al[1], ab + 144 * 144 + col);           // s=1, mi=1
#pragma unroll
            for (int f = 0; f < 8; f++) {
                u32 bh[2], bl[2];
                ldmx2(bh, bb + f * 8 * 144 + col);                       // xh
                ldmx2(bl, bb + SX_ROWS * 144 + f * 8 * 144 + col);       // xl
                mma16816(acc[0][f], ah[0], bh);
                mma16816(acc[0][f], al[0], bh);
                mma16816(acc[0][f], ah[0], bl);
                mma16816(acc[1][f], ah[1], bh);
                mma16816(acc[1][f], al[1], bh);
                mma16816(acc[1][f], ah[1], bl);
            }
        }

        if (t < 8) CP_WAIT0();
        __syncthreads();
    }

    // ---- epilogue: D fragments -> y (+bias), mask ww>=62 ----
    int g = lane >> 2, tg = lane & 3;
    int oh = oh0 + wn;                                     // always < 62
#pragma unroll
    for (int mi = 0; mi < 2; mi++) {
        int k0 = m0 + 16 * mi + g;
        float bv0 = bias[k0], bv1 = bias[k0 + 8];
        float* base0 = y + (size_t)(b * KOUT + k0) * LOC + oh * OWW;
#pragma unroll
        for (int f = 0; f < 8; f++) {
            int ww = f * 8 + tg * 2;
            if (ww <= 60) {
                float2 v0 = make_float2(acc[mi][f][0] + bv0, acc[mi][f][1] + bv0);
                float2 v1 = make_float2(acc[mi][f][2] + bv1, acc[mi][f][3] + bv1);
                *(float2*)(base0 + ww) = v0;
                *(float2*)(base0 + (size_t)8 * LOC + ww) = v1;
            }
        }
    }
}

// ---------------- 5) argmax + near-tie detection ----------------
__global__ void argmax_kernel(const float* __restrict__ y) {
    int gloc = blockIdx.x * 128 + threadIdx.x;     // 961*128 == BL exactly
    int b = gloc / LOC;
    int il = gloc - b * LOC;
    const float* yb = y + (size_t)b * KOUT * LOC + il;
    float best = yb[0], second = -3.4e38f;
    int bk = 0;
#pragma unroll 4
    for (int k = 1; k < KOUT; k++) {
        float v = yb[(size_t)k * LOC];
        if (v > best) { second = best; best = v; bk = k; }
        else if (v > second) { second = v; }
    }
    g_winner[gloc] = bk;
    if (best - second < RTHRESH) {
        int idx = atomicAdd(&g_nrefine, 1);
        g_refine[idx] = gloc;
    }
}

// ---------------- 6) exact fp32 rescue of near-tie winners ----------------
__global__ __launch_bounds__(128)
void refine_kernel(const float* __restrict__ x) {
    __shared__ float patch[RDIM][16];
    __shared__ int soff[16];
    __shared__ float rv[128];
    __shared__ int rk[128];
    int tid = threadIdx.x;
    int n = g_nrefine;

    for (int base = blockIdx.x * 16; base < n; base += gridDim.x * 16) {
        int cnt = min(16, n - base);
        if (tid < 16) {
            int off = -1;
            if (tid < cnt) {
                int gloc = g_refine[base + tid];
                int b = gloc / LOC;
                int il = gloc - b * LOC;
                int oh = il / OWW, ow = il - oh * OWW;
                off = b * (CIN * HW) + oh * WIN + ow;
            }
            soff[tid] = off;
        }
        __syncthreads();
        // stage 16 patches
        for (int e = tid; e < RDIM * 16; e += 128) {
            int r = e >> 4, p = e & 15;
            int off = soff[p];
            float v = 0.f;
            if (off >= 0) {
                int c = r / 9, rem = r % 9;
                v = x[off + c * HW + (rem / 3) * WIN + (rem % 3)];
            }
            patch[r][p] = v;
        }
        __syncthreads();
        // thread = k: exact fp32 dot for all 16 locations
        float acc[16];
#pragma unroll
        for (int p = 0; p < 16; p++) acc[p] = 0.f;
        for (int r = 0; r < RDIM; r++) {
            float wv = g_wT[r * KOUT + tid];           // coalesced
            const float4* pr = (const float4*)&patch[r][0];
            float4 p0 = pr[0], p1 = pr[1], p2 = pr[2], p3 = pr[3];
            acc[0]  += wv * p0.x;  acc[1]  += wv * p0.y;  acc[2]  += wv * p0.z;  acc[3]  += wv * p0.w;
            acc[4]  += wv * p1.x;  acc[5]  += wv * p1.y;  acc[6]  += wv * p1.z;  acc[7]  += wv * p1.w;
            acc[8]  += wv * p2.x;  acc[9]  += wv * p2.y;  acc[10] += wv * p2.z;  acc[11] += wv * p2.w;
            acc[12] += wv * p3.x;  acc[13] += wv * p3.y;  acc[14] += wv * p3.z;  acc[15] += wv * p3.w;
        }
        // per-location block argmax (first-max tiebreak: smaller k)
        for (int p = 0; p < cnt; p++) {
            rv[tid] = acc[p];
            rk[tid] = tid;
            __syncthreads();
            for (int off = 64; off > 0; off >>= 1) {
                if (tid < off) {
                    float v2 = rv[tid + off];
                    int k2 = rk[tid + off];
                    if (v2 > rv[tid] || (v2 == rv[tid] && k2 < rk[tid])) {
                        rv[tid] = v2; rk[tid] = k2;
                    }
                }
                __syncthreads();
            }
            if (tid == 0) g_winner[g_refine[base + p]] = rk[0];
            __syncthreads();
        }
        __syncthreads();
    }
}

// ---------------- 7) winner counts ----------------
__global__ void count_kernel() {
    __shared__ int sc[KOUT];
    int t = threadIdx.x;
    sc[t] = 0;
    __syncthreads();
    atomicAdd(&sc[g_winner[blockIdx.x * 128 + t]], 1);
    __syncthreads();
    if (sc[t]) atomicAdd(&g_counts[t], sc[t]);
}

// ---------------- 8) exclusive scan of counts ----------------
__global__ void scan_kernel() {
    int t = threadIdx.x;               // 128
    int lane = t & 31, w = t >> 5;
    int v = g_counts[t];
    int inc = v;
#pragma unroll
    for (int o = 1; o < 32; o <<= 1) {
        int n = __shfl_up_sync(0xffffffffu, inc, o);
        if (lane >= o) inc += n;
    }
    __shared__ int wsum[4];
    if (lane == 31) wsum[w] = inc;
    __syncthreads();
    int add = 0;
#pragma unroll
    for (int i = 0; i < 4; i++) if (i < w) add += wsum[i];
    int excl = inc - v + add;
    g_offsets[t] = excl;
    g_cursor[t] = excl;
    if (t == 127) g_offsets[KOUT] = excl + v;
}

// ---------------- 9) scatter locations into per-k lists ----------------
__global__ void scatter_kernel() {
    int gloc = blockIdx.x * 128 + threadIdx.x;
    int k = g_winner[gloc];
    unsigned m = __match_any_sync(0xffffffffu, k);
    int lane = threadIdx.x & 31;
    int leader = __ffs(m) - 1;
    int prefix = __popc(m & ((1u << lane) - 1u));
    int base = 0;
    if (lane == leader) base = atomicAdd(&g_cursor[k], __popc(m));
    base = __shfl_sync(0xffffffffu, base, leader);
    g_list[base + prefix] = gloc;
}

// ---------------- 10) Hebbian gather ----------------
#define NSPLIT 8
__global__ __launch_bounds__(192)
void hebb_kernel(const float* __restrict__ x, float* __restrict__ wu) {
    int k = blockIdx.y;
    int start = g_offsets[k], end = g_offsets[k + 1];
    int len = end - start;
    int s0 = start + (int)((long long)len * blockIdx.x / NSPLIT);
    int s1 = start + (int)((long long)len * (blockIdx.x + 1) / NSPLIT);
    int t = threadIdx.x;

    int off[3];
    float a[3] = {0.f, 0.f, 0.f};
#pragma unroll
    for (int q = 0; q < 3; q++) {
        int r = t + q * 192;
        int c = r / 9, rem = r % 9;
        off[q] = c * HW + (rem / 3) * WIN + (rem % 3);
    }

    if (s0 < s1) {
        int nextg = g_list[s0];
        for (int p = s0; p < s1; p++) {
            int gloc = nextg;
            if (p + 1 < s1) nextg = g_list[p + 1];
            int b = gloc / LOC;
            int il = gloc - b * LOC;
            int oh = il / OWW;
            int ow = il - oh * OWW;
            const float* px = x + (size_t)b * (CIN * HW) + oh * WIN + ow;
            a[0] += px[off[0]];
            a[1] += px[off[1]];
            a[2] += px[off[2]];
        }
    }

    const float scale = 1.0f / 123008.0f;
#pragma unroll
    for (int q = 0; q < 3; q++)
        atomicAdd(&wu[k * RDIM + t + q * 192], a[q] * scale);
}

// ---------------- launch ----------------
extern "C" void kernel_launch(void* const* d_in, const int* in_sizes, int n_in,
                              void* d_out, int out_size) {
    const float* x    = (const float*)d_in[0];   // [32,64,64,64]
    const float* w    = (const float*)d_in[1];   // [128,64,3,3]
    const float* bias = (const float*)d_in[2];   // [128]
    float* y  = (float*)d_out;                   // [32,128,62,62]
    float* wu = y + (size_t)Y_ELEMS;             // [128,64,3,3]

    cudaFuncSetAttribute(conv_mma_kernel, cudaFuncAttributeMaxDynamicSharedMemorySize, SMEM_BYTES);

    norm_kernel<<<KOUT, 256>>>(w);                              // 1
    wbuild_kernel<<<50, 256>>>(w, wu);                          // 2
    xbuild_kernel<<<2048, 256>>>(x);                            // 3
    conv_mma_kernel<<<dim3(31, 32), 256, SMEM_BYTES>>>(bias, y);// 4 <- profiled slot
    argmax_kernel<<<BL / 128, 128>>>(y);                        // 5
    refine_kernel<<<128, 128>>>(x);                             // 6
    count_kernel<<<BL / 128, 128>>>();                          // 7
    scan_kernel<<<1, 128>>>();                                  // 8
    scatter_kernel<<<BL / 128, 128>>>();                        // 9
    hebb_kernel<<<dim3(NSPLIT, KOUT), 192>>>(x, wu);            // 10
}